// round 14
// baseline (speedup 1.0000x reference)
#include <cuda_runtime.h>
#include <cuda_bf16.h>

#define NEGV (-1e9f)
#define B_   32
#define N_   256
#define CH   2048
#define ROWS (B_ * N_)                 /* 8192 */
#define KT   16

/* plane strides (elements) */
#define PFEAT 8388608LL                /* 8192x1024 */
#define PW0   2097152LL                /* 1024x2048 tr-> 2048x1024 */
#define PADJ  2097152LL                /* 32x256x256 */
#define PBIG  16777216LL               /* 8192x2048 class */
#define PAAF  4194304LL                /* 2048x2048 */
#define PWC   8388608LL                /* 2048x4096 (Wc tr) */
#define PSB   2097152LL                /* 32x256x256 */

/* smem geometry: padded rows 24 bf16 = 48 B; 4 plane-tiles per stage */
#define APAD_B  48
#define ATILE_B (128 * APAD_B)         /* 6144 B */
#define STG_B   (4 * ATILE_B)          /* 24576 B */
#define NSTG    3
#define SMEMT   (NSTG * STG_B)         /* 73728 B */

/* ------------- scratch (device globals) --------------------------------- */
__device__ __nv_bfloat16 g_bfA [2LL * 8192 * 2048];
__device__ __nv_bfloat16 g_bfB [2LL * 8192 * 2048];
__device__ __nv_bfloat16 g_bfB2[2LL * 8192 * 2048];
__device__ float g_ax[ROWS * CH];
__device__ float g_ux[ROWS * CH];
__device__ float g_e1[ROWS * CH];
__device__ float g_e2[ROWS * CH];
__device__ float g_tb[ROWS * CH];
__device__ float g_m1[ROWS * CH];
__device__ float g_m2[ROWS * CH];
__device__ float g_sb[B_ * N_ * N_];
__device__ float g_col[2 * ROWS];

/* ------------- low-level helpers ---------------------------------------- */
__device__ __forceinline__ void cpasync16(unsigned saddr, const void* g) {
    asm volatile("cp.async.ca.shared.global [%0], [%1], 16;" :: "r"(saddr), "l"(g));
}
#define LDSM4(r, addr) \
    asm volatile("ldmatrix.sync.aligned.m8n8.x4.shared.b16 {%0,%1,%2,%3}, [%4];" \
        : "=r"((r)[0]), "=r"((r)[1]), "=r"((r)[2]), "=r"((r)[3]) : "r"(addr))
#define MMA(d, a, b0v, b1v) \
    asm volatile("mma.sync.aligned.m16n8k16.row.col.f32.bf16.bf16.f32 " \
        "{%0,%1,%2,%3},{%4,%5,%6,%7},{%8,%9},{%0,%1,%2,%3};" \
        : "+f"((d)[0]), "+f"((d)[1]), "+f"((d)[2]), "+f"((d)[3]) \
        : "r"((a)[0]), "r"((a)[1]), "r"((a)[2]), "r"((a)[3]), "r"(b0v), "r"(b1v))

/* ------------- tensor GEMM: C = A @ Bop^T, bf16x2 split, 3 products.
 * A planes: [M][lda] bf16 x2 (plane stride aPS); Bop planes: [N][ldb] x2.
 * CTA tile 128x128, 8 warps (warp tile 32x64), K-step 16, 3-stage cp.async.
 * a0*b0 -> cm (dominant, clean fp32 chain); a0b1 + a1b0 -> cc.
 * MMAs issued in 3 passes of 16 so consecutive writes to one accumulator
 * are >=16 independent HMMAs apart -> no RAW stalls (asm order = SASS order). */
__global__ __launch_bounds__(256) void tgemm(
    int M, int N, int K,
    const __nv_bfloat16* __restrict__ A, int lda, long long aPS, long long sAb,
    const __nv_bfloat16* __restrict__ B, int ldb, long long bPS, long long sBb,
    float* __restrict__ C, int ldc, long long sCb,
    const float* __restrict__ bias, int relu,
    const float* __restrict__ rowscale,
    const float* __restrict__ addend, int ldadd, long long sAddb)
{
    extern __shared__ unsigned char smem[];
    const int bz = blockIdx.z;
    A += (long long)bz * sAb;
    B += (long long)bz * sBb;
    C += (long long)bz * sCb;
    if (addend) addend += (long long)bz * sAddb;
    const int m0 = blockIdx.x * 128, n0 = blockIdx.y * 128;
    const int tid = threadIdx.x, lane = tid & 31, wid = tid >> 5;
    const unsigned sb = (unsigned)__cvta_generic_to_shared(smem);

    /* cp.async mapping: thread -> (row, 16B chunk) for both A and B tiles */
    const int cr = tid >> 1, ck = tid & 1;
    const __nv_bfloat16* aG = A + (long long)(m0 + cr) * lda + ck * 8;
    const __nv_bfloat16* bG = B + (long long)(n0 + cr) * ldb + ck * 8;
    const unsigned aS = sb + cr * APAD_B + ck * 16;
    const unsigned bS = sb + 2 * ATILE_B + cr * APAD_B + ck * 16;

    const int nst = K >> 4;
#define TISSUE(t, st) do {                                                \
        long long ko = (long long)(t) * KT;                               \
        _Pragma("unroll")                                                 \
        for (int p = 0; p < 2; p++) {                                     \
            cpasync16(aS + (st) * STG_B + p * ATILE_B, aG + p * aPS + ko);\
            cpasync16(bS + (st) * STG_B + p * ATILE_B, bG + p * bPS + ko);\
        }                                                                 \
        asm volatile("cp.async.commit_group;");                           \
    } while (0)

    TISSUE(0, 0);
    if (nst > 1) TISSUE(1, 1);

    float cm[2][8][4], cc[2][8][4];
#pragma unroll
    for (int i = 0; i < 2; i++)
#pragma unroll
        for (int j = 0; j < 8; j++)
#pragma unroll
            for (int k = 0; k < 4; k++) { cm[i][j][k] = 0.f; cc[i][j][k] = 0.f; }

    const int mw = (wid & 3) * 32, nw = (wid >> 2) * 64;
    const int q = lane >> 3, rl = lane & 7;
    const unsigned aoff = (mw + rl + (q & 1) * 8) * APAD_B + (q >> 1) * 16;
    const unsigned boff = 2 * ATILE_B + (nw + rl + (q & 1) * 8) * APAD_B + (q >> 1) * 16;

    int st = 0;
    for (int t = 0; t < nst; ++t) {
        if (t + 1 < nst) asm volatile("cp.async.wait_group 1;");
        else             asm volatile("cp.async.wait_group 0;");
        __syncthreads();
        if (t + 2 < nst) {
            int s2 = st + 2; if (s2 >= NSTG) s2 -= NSTG;
            TISSUE(t + 2, s2);
        }
        const unsigned sa = sb + st * STG_B + aoff;
        const unsigned sB2 = sb + st * STG_B + boff;

        unsigned a[2][2][4];
#pragma unroll
        for (int p = 0; p < 2; p++)
#pragma unroll
            for (int mi = 0; mi < 2; mi++)
                LDSM4(a[p][mi], sa + p * ATILE_B + mi * 16 * APAD_B);

        unsigned bf[2][4][4];
#pragma unroll
        for (int p = 0; p < 2; p++)
#pragma unroll
            for (int ng = 0; ng < 4; ng++)
                LDSM4(bf[p][ng], sB2 + p * ATILE_B + ng * 16 * APAD_B);

        /* pass 0: dominant a0*b0 -> cm (16 independent MMAs) */
#pragma unroll
        for (int ng = 0; ng < 4; ng++)
#pragma unroll
            for (int mi = 0; mi < 2; mi++)
#pragma unroll
                for (int j = 0; j < 2; j++)
                    MMA(cm[mi][ng * 2 + j], a[0][mi], bf[0][ng][j], bf[0][ng][j + 2]);
        /* pass 1: a0*b1 -> cc (16 independent MMAs) */
#pragma unroll
        for (int ng = 0; ng < 4; ng++)
#pragma unroll
            for (int mi = 0; mi < 2; mi++)
#pragma unroll
                for (int j = 0; j < 2; j++)
                    MMA(cc[mi][ng * 2 + j], a[0][mi], bf[1][ng][j], bf[1][ng][j + 2]);
        /* pass 2: a1*b0 -> cc (revisits cc 16 MMAs later -> RAW hidden) */
#pragma unroll
        for (int ng = 0; ng < 4; ng++)
#pragma unroll
            for (int mi = 0; mi < 2; mi++)
#pragma unroll
                for (int j = 0; j < 2; j++)
                    MMA(cc[mi][ng * 2 + j], a[1][mi], bf[0][ng][j], bf[0][ng][j + 2]);

        __syncthreads();
        if (++st == NSTG) st = 0;
    }
#undef TISSUE

    /* epilogue: c-frag (mi): rows g/g+8, cols tg*2, tg*2+1 */
    const int g = lane >> 2, tg = lane & 3;
#pragma unroll
    for (int mi = 0; mi < 2; mi++) {
        const int r0 = m0 + mw + mi * 16 + g;
        const int r1 = r0 + 8;
        const float rs0 = rowscale ? rowscale[r0] : 1.f;
        const float rs1 = rowscale ? rowscale[r1] : 1.f;
#pragma unroll
        for (int nf = 0; nf < 8; nf++) {
            const int col = n0 + nw + nf * 8 + tg * 2;
            float o0 = cm[mi][nf][0] + cc[mi][nf][0];
            float o1 = cm[mi][nf][1] + cc[mi][nf][1];
            float o2 = cm[mi][nf][2] + cc[mi][nf][2];
            float o3 = cm[mi][nf][3] + cc[mi][nf][3];
            if (bias) {
                float bv0 = bias[col], bv1 = bias[col + 1];
                o0 += bv0; o1 += bv1; o2 += bv0; o3 += bv1;
            }
            if (relu) {
                o0 = fmaxf(o0, 0.f); o1 = fmaxf(o1, 0.f);
                o2 = fmaxf(o2, 0.f); o3 = fmaxf(o3, 0.f);
            }
            o0 *= rs0; o1 *= rs0; o2 *= rs1; o3 *= rs1;
            if (addend) {
                o0 += addend[(long long)r0 * ldadd + col];
                o1 += addend[(long long)r0 * ldadd + col + 1];
                o2 += addend[(long long)r1 * ldadd + col];
                o3 += addend[(long long)r1 * ldadd + col + 1];
            }
            *(float2*)(C + (long long)r0 * ldc + col) = make_float2(o0, o1);
            *(float2*)(C + (long long)r1 * ldc + col) = make_float2(o2, o3);
        }
    }
}

/* ------------- fp32 -> 2 bf16 planes ------------------------------------ */
__device__ __forceinline__ void split2(float v, __nv_bfloat16& b0, __nv_bfloat16& b1) {
    b0 = __float2bfloat16(v);
    b1 = __float2bfloat16(v - __bfloat162float(b0));
}
__global__ void split_rm(const float* __restrict__ in, __nv_bfloat16* __restrict__ out,
                         long long n, long long PS)
{
    long long i = (long long)blockIdx.x * blockDim.x + threadIdx.x;
    if (i >= n) return;
    __nv_bfloat16 b0, b1;
    split2(in[i], b0, b1);
    out[i] = b0; out[PS + i] = b1;
}
/* transpose + split: in [z][R][C] fp32 -> planes [z][C][R] bf16 */
__global__ void split_tr(const float* __restrict__ in, __nv_bfloat16* __restrict__ out,
                         int R, int C, long long PS)
{
    __shared__ float t[32][33];
    const long long zo = (long long)blockIdx.z * R * C;
    const float* ip = in + zo;
    __nv_bfloat16* op = out + zo;
    int x = blockIdx.x * 32 + threadIdx.x;
    int y0 = blockIdx.y * 32 + threadIdx.y;
#pragma unroll
    for (int j = 0; j < 32; j += 8)
        t[threadIdx.y + j][threadIdx.x] = ip[(long long)(y0 + j) * C + x];
    __syncthreads();
    int xo = blockIdx.y * 32 + threadIdx.x;
    int yo = blockIdx.x * 32 + threadIdx.y;
#pragma unroll
    for (int j = 0; j < 32; j += 8) {
        __nv_bfloat16 b0, b1;
        split2(t[threadIdx.x][threadIdx.y + j], b0, b1);
        long long oi = (long long)(yo + j) * R + xo;
        op[oi] = b0; op[PS + oi] = b1;
    }
}

/* ------------- colnorm --------------------------------------------------- */
__global__ void colnorm_kernel(const float* __restrict__ A, float* __restrict__ inv)
{
    int g = blockIdx.x * blockDim.x + threadIdx.x;
    int b = g >> 8, m = g & 255;
    const float* base = A + (long long)b * 65536 + m;
    float s = 0.f;
#pragma unroll 8
    for (int n = 0; n < 256; n++) s += fabsf(base[n * 256]);
    inv[g] = 1.f / fmaxf(s, 1e-12f);
}

/* ------------- masked Sinkhorn ------------------------------------------- */
__global__ __launch_bounds__(1024) void sinkhorn_kernel(
    float* __restrict__ buf, float* __restrict__ out,
    const int* __restrict__ n1, const int* __restrict__ iters_ptr)
{
    __shared__ float red[4 * 256];
    __shared__ float lsebuf[256];
    const int b = blockIdx.x;
    float* Mb = buf + (long long)b * 65536;
    const int nv = n1[b];
    const int iters = *iters_ptr;
    const int tid = threadIdx.x;
    const int warp = tid >> 5, lane = tid & 31;

    for (int idx = tid; idx < 65536; idx += 1024) {
        int r = idx >> 8;
        float v = Mb[idx];
        Mb[idx] = (r < nv) ? v / 0.05f : NEGV;
    }
    __syncthreads();
    for (int it = 0; it < iters; ++it) {
        if ((it & 1) == 0) {
            for (int r = warp; r < 256; r += 32) {
                float* rp = Mb + (r << 8);
                float v[8];
#pragma unroll
                for (int j = 0; j < 8; j++) v[j] = rp[lane + (j << 5)];
                float mx = v[0];
#pragma unroll
                for (int j = 1; j < 8; j++) mx = fmaxf(mx, v[j]);
#pragma unroll
                for (int o = 16; o > 0; o >>= 1)
                    mx = fmaxf(mx, __shfl_xor_sync(0xffffffffu, mx, o));
                float sm = 0.f;
#pragma unroll
                for (int j = 0; j < 8; j++) sm += expf(v[j] - mx);
#pragma unroll
                for (int o = 16; o > 0; o >>= 1)
                    sm += __shfl_xor_sync(0xffffffffu, sm, o);
                float lse = mx + logf(sm);
                bool ok = r < nv;
#pragma unroll
                for (int j = 0; j < 8; j++)
                    rp[lane + (j << 5)] = ok ? (v[j] - lse) : NEGV;
            }
            __syncthreads();
        } else {
            const int c = tid & 255, g = tid >> 8;
            float pm = NEGV;
            for (int r = g; r < 256; r += 4) pm = fmaxf(pm, Mb[(r << 8) + c]);
            red[(g << 8) + c] = pm;
            __syncthreads();
            if (tid < 256)
                lsebuf[tid] = fmaxf(fmaxf(red[tid], red[256 + tid]),
                                    fmaxf(red[512 + tid], red[768 + tid]));
            __syncthreads();
            float cm = lsebuf[c];
            float ps = 0.f;
            for (int r = g; r < 256; r += 4) ps += expf(Mb[(r << 8) + c] - cm);
            red[(g << 8) + c] = ps;
            __syncthreads();
            if (tid < 256)
                lsebuf[tid] = lsebuf[tid] + logf(red[tid] + red[256 + tid] +
                                                 red[512 + tid] + red[768 + tid]);
            __syncthreads();
            for (int idx = tid; idx < 65536; idx += 1024) {
                int r = idx >> 8, cc2 = idx & 255;
                Mb[idx] = (r < nv) ? (Mb[idx] - lsebuf[cc2]) : NEGV;
            }
            __syncthreads();
        }
    }
    float* ob = out + (long long)b * 65536;
    for (int idx = tid; idx < 65536; idx += 1024)
        ob[idx] = expf(Mb[idx]);
}

/* ------------- orchestration -------------------------------------------- */
extern "C" void kernel_launch(void* const* d_in, const int* in_sizes, int n_in,
                              void* d_out, int out_size)
{
    (void)in_sizes; (void)n_in; (void)out_size;
    const float* feat1 = (const float*)d_in[0];
    const float* feat2 = (const float*)d_in[1];
    const float* A1p   = (const float*)d_in[2];
    const float* A2p   = (const float*)d_in[3];
    const int*   n1p   = (const int*)d_in[4];
    const int*   skp   = (const int*)d_in[7];
    const float* W0a = (const float*)d_in[8],  *b0a = (const float*)d_in[9];
    const float* W0u = (const float*)d_in[10], *b0u = (const float*)d_in[11];
    const float* W1a = (const float*)d_in[12], *b1a = (const float*)d_in[13];
    const float* W1u = (const float*)d_in[14], *b1u = (const float*)d_in[15];
    const float* Wc  = (const float*)d_in[16], *bc  = (const float*)d_in[17];
    const float* Aaff0 = (const float*)d_in[18];
    const float* Aaff1 = (const float*)d_in[19];
    float* outp = (float*)d_out;

    __nv_bfloat16 *bfA, *bfB, *bfB2;
    float *ax, *ux, *e1, *e2, *tb, *m1, *m2, *sb, *col;
    cudaGetSymbolAddress((void**)&bfA,  g_bfA);
    cudaGetSymbolAddress((void**)&bfB,  g_bfB);
    cudaGetSymbolAddress((void**)&bfB2, g_bfB2);
    cudaGetSymbolAddress((void**)&ax,  g_ax);
    cudaGetSymbolAddress((void**)&ux,  g_ux);
    cudaGetSymbolAddress((void**)&e1,  g_e1);
    cudaGetSymbolAddress((void**)&e2,  g_e2);
    cudaGetSymbolAddress((void**)&tb,  g_tb);
    cudaGetSymbolAddress((void**)&m1,  g_m1);
    cudaGetSymbolAddress((void**)&m2,  g_m2);
    cudaGetSymbolAddress((void**)&sb,  g_sb);
    cudaGetSymbolAddress((void**)&col, g_col);

    cudaFuncSetAttribute(tgemm, cudaFuncAttributeMaxDynamicSharedMemorySize, SMEMT);

    const dim3 T32(32, 8);
    const long long SE = 524288;            /* 256*2048 per-batch */
    const long long SS = 65536;

    colnorm_kernel<<<32, 256>>>(A1p, col);
    colnorm_kernel<<<32, 256>>>(A2p, col + ROWS);

    /* gconv layer 0 : graph g = 1,2 */
    for (int g = 0; g < 2; g++) {
        const float* feat = g ? feat2 : feat1;
        const float* Ap   = g ? A2p : A1p;
        float* ev         = g ? e2 : e1;
        const float* cv   = col + g * ROWS;
        split_rm<<<32768, 256>>>(feat, bfA, 8192LL * 1024, PFEAT);
        split_tr<<<dim3(64, 32, 1), T32>>>(W0a, bfB, 1024, 2048, PW0);
        tgemm<<<dim3(64, 16, 1), 256, SMEMT>>>(8192, 2048, 1024, bfA, 1024, PFEAT, 0,
            bfB, 1024, PW0, 0, ax, 2048, 0, b0a, 1, cv, 0, 0, 0);
        split_tr<<<dim3(64, 32, 1), T32>>>(W0u, bfB, 1024, 2048, PW0);
        tgemm<<<dim3(64, 16, 1), 256, SMEMT>>>(8192, 2048, 1024, bfA, 1024, PFEAT, 0,
            bfB, 1024, PW0, 0, ux, 2048, 0, b0u, 1, 0, 0, 0, 0);
        split_rm<<<8192, 256>>>(Ap, bfA, 2097152LL, PADJ);
        split_tr<<<dim3(64, 8, 32), T32>>>(ax, bfB2, 256, 2048, PBIG);
        tgemm<<<dim3(2, 16, 32), 256, SMEMT>>>(256, 2048, 256, bfA, 256, PADJ, SS,
            bfB2, 256, PBIG, SE, ev, 2048, SE, 0, 0, 0, ux, 2048, SE);
    }

    /* affinity 0 + sinkhorn */
    split_rm<<<65536, 256>>>(e1, bfA, (long long)ROWS * CH, PBIG);
    split_tr<<<dim3(64, 64, 1), T32>>>(Aaff0, bfB, 2048, 2048, PAAF);
    tgemm<<<dim3(64, 16, 1), 256, SMEMT>>>(8192, 2048, 2048, bfA, 2048, PBIG, 0,
        bfB, 2048, PAAF, 0, tb, 2048, 0, 0, 0, 0, 0, 0, 0);
    split_rm<<<65536, 256>>>(tb, bfA, (long long)ROWS * CH, PBIG);
    split_rm<<<65536, 256>>>(e2, bfB, (long long)ROWS * CH, PBIG);
    tgemm<<<dim3(2, 2, 32), 256, SMEMT>>>(256, 256, 2048, bfA, 2048, PBIG, SE,
        bfB, 2048, PBIG, SE, sb, 256, SS, 0, 0, 0, 0, 0, 0);
    sinkhorn_kernel<<<32, 1024>>>(sb, sb, n1p, skp);

    /* cross update: m1 = e1@WcT + (s@e2)@WcB + bc ; m2 = e2@WcT + (sT@e1)@WcB + bc */
    split_rm<<<8192, 256>>>(sb, bfA, 2097152LL, PSB);
    split_tr<<<dim3(64, 8, 32), T32>>>(e2, bfB2, 256, 2048, PBIG);
    tgemm<<<dim3(2, 16, 32), 256, SMEMT>>>(256, 2048, 256, bfA, 256, PSB, SS,
        bfB2, 256, PBIG, SE, tb, 2048, SE, 0, 0, 0, 0, 0, 0);     /* u -> tb */
    split_tr<<<dim3(64, 128, 1), T32>>>(Wc, bfB, 4096, 2048, PWC);
    split_rm<<<65536, 256>>>(e1, bfA, (long long)ROWS * CH, PBIG);
    tgemm<<<dim3(64, 16, 1), 256, SMEMT>>>(8192, 2048, 2048, bfA, 2048, PBIG, 0,
        bfB, 4096, PWC, 0, m1, 2048, 0, bc, 0, 0, 0, 0, 0);
    split_rm<<<65536, 256>>>(tb, bfA, (long long)ROWS * CH, PBIG);
    tgemm<<<dim3(64, 16, 1), 256, SMEMT>>>(8192, 2048, 2048, bfA, 2048, PBIG, 0,
        bfB + 2048, 4096, PWC, 0, m1, 2048, 0, 0, 0, 0, m1, 2048, 0);
    split_tr<<<dim3(8, 8, 32), T32>>>(sb, bfA, 256, 256, PSB);    /* sT planes */
    split_tr<<<dim3(64, 8, 32), T32>>>(e1, bfB2, 256, 2048, PBIG);
    tgemm<<<dim3(2, 16, 32), 256, SMEMT>>>(256, 2048, 256, bfA, 256, PSB, SS,
        bfB2, 256, PBIG, SE, ax, 2048, SE, 0, 0, 0, 0, 0, 0);     /* v -> ax */
    split_rm<<<65536, 256>>>(e2, bfA, (long long)ROWS * CH, PBIG);
    tgemm<<<dim3(64, 16, 1), 256, SMEMT>>>(8192, 2048, 2048, bfA, 2048, PBIG, 0,
        bfB, 4096, PWC, 0, m2, 2048, 0, bc, 0, 0, 0, 0, 0);
    split_rm<<<65536, 256>>>(ax, bfA, (long long)ROWS * CH, PBIG);
    tgemm<<<dim3(64, 16, 1), 256, SMEMT>>>(8192, 2048, 2048, bfA, 2048, PBIG, 0,
        bfB + 2048, 4096, PWC, 0, m2, 2048, 0, 0, 0, 0, m2, 2048, 0);

    /* gconv layer 1 */
    for (int g = 0; g < 2; g++) {
        const float* mv = g ? m2 : m1;
        const float* Ap = g ? A2p : A1p;
        float* ev       = g ? e2 : e1;
        const float* cv = col + g * ROWS;
        split_rm<<<65536, 256>>>(mv, bfA, (long long)ROWS * CH, PBIG);
        split_tr<<<dim3(64, 64, 1), T32>>>(W1a, bfB, 2048, 2048, PAAF);
        tgemm<<<dim3(64, 16, 1), 256, SMEMT>>>(8192, 2048, 2048, bfA, 2048, PBIG, 0,
            bfB, 2048, PAAF, 0, ax, 2048, 0, b1a, 1, cv, 0, 0, 0);
        split_tr<<<dim3(64, 64, 1), T32>>>(W1u, bfB, 2048, 2048, PAAF);
        tgemm<<<dim3(64, 16, 1), 256, SMEMT>>>(8192, 2048, 2048, bfA, 2048, PBIG, 0,
            bfB, 2048, PAAF, 0, ux, 2048, 0, b1u, 1, 0, 0, 0, 0);
        split_rm<<<8192, 256>>>(Ap, bfA, 2097152LL, PADJ);
        split_tr<<<dim3(64, 8, 32), T32>>>(ax, bfB2, 256, 2048, PBIG);
        tgemm<<<dim3(2, 16, 32), 256, SMEMT>>>(256, 2048, 256, bfA, 256, PADJ, SS,
            bfB2, 256, PBIG, SE, ev, 2048, SE, 0, 0, 0, ux, 2048, SE);
    }

    /* affinity 1 + final sinkhorn */
    split_rm<<<65536, 256>>>(e1, bfA, (long long)ROWS * CH, PBIG);
    split_tr<<<dim3(64, 64, 1), T32>>>(Aaff1, bfB, 2048, 2048, PAAF);
    tgemm<<<dim3(64, 16, 1), 256, SMEMT>>>(8192, 2048, 2048, bfA, 2048, PBIG, 0,
        bfB, 2048, PAAF, 0, tb, 2048, 0, 0, 0, 0, 0, 0, 0);
    split_rm<<<65536, 256>>>(tb, bfA, (long long)ROWS * CH, PBIG);
    split_rm<<<65536, 256>>>(e2, bfB, (long long)ROWS * CH, PBIG);
    tgemm<<<dim3(2, 2, 32), 256, SMEMT>>>(256, 256, 2048, bfA, 2048, PBIG, SE,
        bfB, 2048, PBIG, SE, sb, 256, SS, 0, 0, 0, 0, 0, 0);
    sinkhorn_kernel<<<32, 1024>>>(sb, outp, n1p, skp);
}

// round 16
// speedup vs baseline: 1.0582x; 1.0582x over previous
#include <cuda_runtime.h>
#include <cuda_bf16.h>

#define NEGV (-1e9f)
#define B_   32
#define N_   256
#define CH   2048
#define ROWS (B_ * N_)                 /* 8192 */
#define KT   16

/* plane strides (elements) */
#define PFEAT 8388608LL                /* 8192x1024 */
#define PW0   2097152LL                /* 1024x2048 tr-> 2048x1024 */
#define PADJ  2097152LL                /* 32x256x256 */
#define PBIG  16777216LL               /* 8192x2048 class */
#define PAAF  4194304LL                /* 2048x2048 */
#define PWC   8388608LL                /* 2048x4096 (Wc tr) */
#define PSB   2097152LL                /* 32x256x256 */

/* smem geometry: padded rows 24 bf16 = 48 B; 4 plane-tiles per stage */
#define APAD_B  48
#define ATILE_B (128 * APAD_B)         /* 6144 B */
#define STG_B   (4 * ATILE_B)          /* 24576 B */
#define NSTG    3
#define SMEMT   (NSTG * STG_B)         /* 73728 B */

/* ------------- scratch (device globals) --------------------------------- */
__device__ __nv_bfloat16 g_bfA [2LL * 8192 * 2048];
__device__ __nv_bfloat16 g_bfB [2LL * 8192 * 2048];
__device__ __nv_bfloat16 g_bfB2[2LL * 8192 * 2048];
__device__ __nv_bfloat16 g_pE1[2LL * ROWS * CH];
__device__ __nv_bfloat16 g_pE2[2LL * ROWS * CH];
__device__ __nv_bfloat16 g_pTB[2LL * ROWS * CH];
__device__ __nv_bfloat16 g_pU [2LL * ROWS * CH];
__device__ __nv_bfloat16 g_pV [2LL * ROWS * CH];
__device__ __nv_bfloat16 g_pM1[2LL * ROWS * CH];
__device__ __nv_bfloat16 g_pM2[2LL * ROWS * CH];
__device__ __nv_bfloat16 g_pADJ[2LL * 2097152];
__device__ __nv_bfloat16 g_pWu [2LL * 4194304];
__device__ float g_ax[ROWS * CH];
__device__ float g_ux[ROWS * CH];
__device__ float g_e1[ROWS * CH];
__device__ float g_e2[ROWS * CH];
__device__ float g_tb[ROWS * CH];
__device__ float g_m1[ROWS * CH];
__device__ float g_m2[ROWS * CH];
__device__ float g_sb[B_ * N_ * N_];
__device__ float g_col[2 * ROWS];

/* ------------- low-level helpers ---------------------------------------- */
__device__ __forceinline__ void cpasync16(unsigned saddr, const void* g) {
    asm volatile("cp.async.ca.shared.global [%0], [%1], 16;" :: "r"(saddr), "l"(g));
}
#define LDSM4(r, addr) \
    asm volatile("ldmatrix.sync.aligned.m8n8.x4.shared.b16 {%0,%1,%2,%3}, [%4];" \
        : "=r"((r)[0]), "=r"((r)[1]), "=r"((r)[2]), "=r"((r)[3]) : "r"(addr))
#define MMA(d, a, b0v, b1v) \
    asm volatile("mma.sync.aligned.m16n8k16.row.col.f32.bf16.bf16.f32 " \
        "{%0,%1,%2,%3},{%4,%5,%6,%7},{%8,%9},{%0,%1,%2,%3};" \
        : "+f"((d)[0]), "+f"((d)[1]), "+f"((d)[2]), "+f"((d)[3]) \
        : "r"((a)[0]), "r"((a)[1]), "r"((a)[2]), "r"((a)[3]), "r"(b0v), "r"(b1v))

__device__ __forceinline__ void split2(float v, __nv_bfloat16& b0, __nv_bfloat16& b1) {
    b0 = __float2bfloat16(v);
    b1 = __float2bfloat16(v - __bfloat162float(b0));
}

/* ------------- tensor GEMM: C = A @ Bop^T, bf16x2 split, 3 products.
 * a0*b0 -> cm (clean fp32 chain); a0b1 + a1b0 -> cc.  R10-proven MMA order.
 * Optional PO: epilogue also writes the bf16 split planes of the result
 * (bit-identical to split_rm) -> downstream GEMMs read planes directly.
 * C may be null (plane-only output).                                      */
__global__ __launch_bounds__(256) void tgemm(
    int M, int N, int K,
    const __nv_bfloat16* __restrict__ A, int lda, long long aPS, long long sAb,
    const __nv_bfloat16* __restrict__ B, int ldb, long long bPS, long long sBb,
    float* __restrict__ C, int ldc, long long sCb,
    const float* __restrict__ bias, int relu,
    const float* __restrict__ rowscale,
    const float* __restrict__ addend, int ldadd, long long sAddb,
    __nv_bfloat16* __restrict__ PO, long long poPS, int pold, long long poSb)
{
    extern __shared__ unsigned char smem[];
    const int bz = blockIdx.z;
    A += (long long)bz * sAb;
    B += (long long)bz * sBb;
    if (C)      C += (long long)bz * sCb;
    if (addend) addend += (long long)bz * sAddb;
    if (PO)     PO += (long long)bz * poSb;
    const int m0 = blockIdx.x * 128, n0 = blockIdx.y * 128;
    const int tid = threadIdx.x, lane = tid & 31, wid = tid >> 5;
    const unsigned sb = (unsigned)__cvta_generic_to_shared(smem);

    const int cr = tid >> 1, ck = tid & 1;
    const __nv_bfloat16* aG = A + (long long)(m0 + cr) * lda + ck * 8;
    const __nv_bfloat16* bG = B + (long long)(n0 + cr) * ldb + ck * 8;
    const unsigned aS = sb + cr * APAD_B + ck * 16;
    const unsigned bS = sb + 2 * ATILE_B + cr * APAD_B + ck * 16;

    const int nst = K >> 4;
#define TISSUE(t, st) do {                                                \
        long long ko = (long long)(t) * KT;                               \
        _Pragma("unroll")                                                 \
        for (int p = 0; p < 2; p++) {                                     \
            cpasync16(aS + (st) * STG_B + p * ATILE_B, aG + p * aPS + ko);\
            cpasync16(bS + (st) * STG_B + p * ATILE_B, bG + p * bPS + ko);\
        }                                                                 \
        asm volatile("cp.async.commit_group;");                           \
    } while (0)

    TISSUE(0, 0);
    if (nst > 1) TISSUE(1, 1);

    float cm[2][8][4], cc[2][8][4];
#pragma unroll
    for (int i = 0; i < 2; i++)
#pragma unroll
        for (int j = 0; j < 8; j++)
#pragma unroll
            for (int k = 0; k < 4; k++) { cm[i][j][k] = 0.f; cc[i][j][k] = 0.f; }

    const int mw = (wid & 3) * 32, nw = (wid >> 2) * 64;
    const int q = lane >> 3, rl = lane & 7;
    const unsigned aoff = (mw + rl + (q & 1) * 8) * APAD_B + (q >> 1) * 16;
    const unsigned boff = 2 * ATILE_B + (nw + rl + (q & 1) * 8) * APAD_B + (q >> 1) * 16;

    int st = 0;
    for (int t = 0; t < nst; ++t) {
        if (t + 1 < nst) asm volatile("cp.async.wait_group 1;");
        else             asm volatile("cp.async.wait_group 0;");
        __syncthreads();
        if (t + 2 < nst) {
            int s2 = st + 2; if (s2 >= NSTG) s2 -= NSTG;
            TISSUE(t + 2, s2);
        }
        const unsigned sa = sb + st * STG_B + aoff;
        const unsigned sB2 = sb + st * STG_B + boff;

        unsigned a[2][2][4];
#pragma unroll
        for (int p = 0; p < 2; p++)
#pragma unroll
            for (int mi = 0; mi < 2; mi++)
                LDSM4(a[p][mi], sa + p * ATILE_B + mi * 16 * APAD_B);

#pragma unroll
        for (int ng = 0; ng < 4; ng++) {
            unsigned bf[2][4];
#pragma unroll
            for (int p = 0; p < 2; p++)
                LDSM4(bf[p], sB2 + p * ATILE_B + ng * 16 * APAD_B);
#pragma unroll
            for (int mi = 0; mi < 2; mi++)
#pragma unroll
                for (int j = 0; j < 2; j++) {
                    float* dm = cm[mi][ng * 2 + j];
                    float* dc = cc[mi][ng * 2 + j];
                    MMA(dm, a[0][mi], bf[0][j], bf[0][j + 2]);
                    MMA(dc, a[0][mi], bf[1][j], bf[1][j + 2]);
                    MMA(dc, a[1][mi], bf[0][j], bf[0][j + 2]);
                }
        }
        __syncthreads();
        if (++st == NSTG) st = 0;
    }
#undef TISSUE

    /* epilogue: c-frag (mi): rows g/g+8, cols tg*2, tg*2+1 */
    const int g = lane >> 2, tg = lane & 3;
#pragma unroll
    for (int mi = 0; mi < 2; mi++) {
        const int r0 = m0 + mw + mi * 16 + g;
        const int r1 = r0 + 8;
        const float rs0 = rowscale ? rowscale[r0] : 1.f;
        const float rs1 = rowscale ? rowscale[r1] : 1.f;
#pragma unroll
        for (int nf = 0; nf < 8; nf++) {
            const int col = n0 + nw + nf * 8 + tg * 2;
            float o0 = cm[mi][nf][0] + cc[mi][nf][0];
            float o1 = cm[mi][nf][1] + cc[mi][nf][1];
            float o2 = cm[mi][nf][2] + cc[mi][nf][2];
            float o3 = cm[mi][nf][3] + cc[mi][nf][3];
            if (bias) {
                float bv0 = bias[col], bv1 = bias[col + 1];
                o0 += bv0; o1 += bv1; o2 += bv0; o3 += bv1;
            }
            if (relu) {
                o0 = fmaxf(o0, 0.f); o1 = fmaxf(o1, 0.f);
                o2 = fmaxf(o2, 0.f); o3 = fmaxf(o3, 0.f);
            }
            o0 *= rs0; o1 *= rs0; o2 *= rs1; o3 *= rs1;
            if (addend) {
                o0 += addend[(long long)r0 * ldadd + col];
                o1 += addend[(long long)r0 * ldadd + col + 1];
                o2 += addend[(long long)r1 * ldadd + col];
                o3 += addend[(long long)r1 * ldadd + col + 1];
            }
            if (C) {
                *(float2*)(C + (long long)r0 * ldc + col) = make_float2(o0, o1);
                *(float2*)(C + (long long)r1 * ldc + col) = make_float2(o2, o3);
            }
            if (PO) {
                __nv_bfloat16 q00, q01, q10, q11, h00, h01, h10, h11;
                split2(o0, q00, h00); split2(o1, q01, h01);
                split2(o2, q10, h10); split2(o3, q11, h11);
                __nv_bfloat162 t;
                t.x = q00; t.y = q01;
                *(__nv_bfloat162*)(PO + (long long)r0 * pold + col) = t;
                t.x = h00; t.y = h01;
                *(__nv_bfloat162*)(PO + poPS + (long long)r0 * pold + col) = t;
                t.x = q10; t.y = q11;
                *(__nv_bfloat162*)(PO + (long long)r1 * pold + col) = t;
                t.x = h10; t.y = h11;
                *(__nv_bfloat162*)(PO + poPS + (long long)r1 * pold + col) = t;
            }
        }
    }
}

/* ------------- split kernels (inputs / transposed operands only) -------- */
__global__ void split_rm(const float* __restrict__ in, __nv_bfloat16* __restrict__ out,
                         long long n, long long PS)
{
    long long i = (long long)blockIdx.x * blockDim.x + threadIdx.x;
    if (i >= n) return;
    __nv_bfloat16 b0, b1;
    split2(in[i], b0, b1);
    out[i] = b0; out[PS + i] = b1;
}
/* transpose + split: in [z][R][C] fp32 -> planes [z][C][R] bf16 */
__global__ void split_tr(const float* __restrict__ in, __nv_bfloat16* __restrict__ out,
                         int R, int C, long long PS)
{
    __shared__ float t[32][33];
    const long long zo = (long long)blockIdx.z * R * C;
    const float* ip = in + zo;
    __nv_bfloat16* op = out + zo;
    int x = blockIdx.x * 32 + threadIdx.x;
    int y0 = blockIdx.y * 32 + threadIdx.y;
#pragma unroll
    for (int j = 0; j < 32; j += 8)
        t[threadIdx.y + j][threadIdx.x] = ip[(long long)(y0 + j) * C + x];
    __syncthreads();
    int xo = blockIdx.y * 32 + threadIdx.x;
    int yo = blockIdx.x * 32 + threadIdx.y;
#pragma unroll
    for (int j = 0; j < 32; j += 8) {
        __nv_bfloat16 b0, b1;
        split2(t[threadIdx.x][threadIdx.y + j], b0, b1);
        long long oi = (long long)(yo + j) * R + xo;
        op[oi] = b0; op[PS + oi] = b1;
    }
}

/* ------------- colnorm --------------------------------------------------- */
__global__ void colnorm_kernel(const float* __restrict__ A, float* __restrict__ inv)
{
    int g = blockIdx.x * blockDim.x + threadIdx.x;
    int b = g >> 8, m = g & 255;
    const float* base = A + (long long)b * 65536 + m;
    float s = 0.f;
#pragma unroll 8
    for (int n = 0; n < 256; n++) s += fabsf(base[n * 256]);
    inv[g] = 1.f / fmaxf(s, 1e-12f);
}

/* ------------- masked Sinkhorn ------------------------------------------- */
__global__ __launch_bounds__(1024) void sinkhorn_kernel(
    float* __restrict__ buf, float* __restrict__ out,
    const int* __restrict__ n1, const int* __restrict__ iters_ptr)
{
    __shared__ float red[4 * 256];
    __shared__ float lsebuf[256];
    const int b = blockIdx.x;
    float* Mb = buf + (long long)b * 65536;
    const int nv = n1[b];
    const int iters = *iters_ptr;
    const int tid = threadIdx.x;
    const int warp = tid >> 5, lane = tid & 31;

    for (int idx = tid; idx < 65536; idx += 1024) {
        int r = idx >> 8;
        float v = Mb[idx];
        Mb[idx] = (r < nv) ? v / 0.05f : NEGV;
    }
    __syncthreads();
    for (int it = 0; it < iters; ++it) {
        if ((it & 1) == 0) {
            for (int r = warp; r < 256; r += 32) {
                float* rp = Mb + (r << 8);
                float v[8];
#pragma unroll
                for (int j = 0; j < 8; j++) v[j] = rp[lane + (j << 5)];
                float mx = v[0];
#pragma unroll
                for (int j = 1; j < 8; j++) mx = fmaxf(mx, v[j]);
#pragma unroll
                for (int o = 16; o > 0; o >>= 1)
                    mx = fmaxf(mx, __shfl_xor_sync(0xffffffffu, mx, o));
                float sm = 0.f;
#pragma unroll
                for (int j = 0; j < 8; j++) sm += expf(v[j] - mx);
#pragma unroll
                for (int o = 16; o > 0; o >>= 1)
                    sm += __shfl_xor_sync(0xffffffffu, sm, o);
                float lse = mx + logf(sm);
                bool ok = r < nv;
#pragma unroll
                for (int j = 0; j < 8; j++)
                    rp[lane + (j << 5)] = ok ? (v[j] - lse) : NEGV;
            }
            __syncthreads();
        } else {
            const int c = tid & 255, g = tid >> 8;
            float pm = NEGV;
            for (int r = g; r < 256; r += 4) pm = fmaxf(pm, Mb[(r << 8) + c]);
            red[(g << 8) + c] = pm;
            __syncthreads();
            if (tid < 256)
                lsebuf[tid] = fmaxf(fmaxf(red[tid], red[256 + tid]),
                                    fmaxf(red[512 + tid], red[768 + tid]));
            __syncthreads();
            float cmv = lsebuf[c];
            float ps = 0.f;
            for (int r = g; r < 256; r += 4) ps += expf(Mb[(r << 8) + c] - cmv);
            red[(g << 8) + c] = ps;
            __syncthreads();
            if (tid < 256)
                lsebuf[tid] = lsebuf[tid] + logf(red[tid] + red[256 + tid] +
                                                 red[512 + tid] + red[768 + tid]);
            __syncthreads();
            for (int idx = tid; idx < 65536; idx += 1024) {
                int r = idx >> 8, cc2 = idx & 255;
                Mb[idx] = (r < nv) ? (Mb[idx] - lsebuf[cc2]) : NEGV;
            }
            __syncthreads();
        }
    }
    float* ob = out + (long long)b * 65536;
    for (int idx = tid; idx < 65536; idx += 1024)
        ob[idx] = expf(Mb[idx]);
}

/* ------------- orchestration -------------------------------------------- */
extern "C" void kernel_launch(void* const* d_in, const int* in_sizes, int n_in,
                              void* d_out, int out_size)
{
    (void)in_sizes; (void)n_in; (void)out_size;
    const float* feat1 = (const float*)d_in[0];
    const float* feat2 = (const float*)d_in[1];
    const float* A1p   = (const float*)d_in[2];
    const float* A2p   = (const float*)d_in[3];
    const int*   n1p   = (const int*)d_in[4];
    const int*   skp   = (const int*)d_in[7];
    const float* W0a = (const float*)d_in[8],  *b0a = (const float*)d_in[9];
    const float* W0u = (const float*)d_in[10], *b0u = (const float*)d_in[11];
    const float* W1a = (const float*)d_in[12], *b1a = (const float*)d_in[13];
    const float* W1u = (const float*)d_in[14], *b1u = (const float*)d_in[15];
    const float* Wc  = (const float*)d_in[16], *bc  = (const float*)d_in[17];
    const float* Aaff0 = (const float*)d_in[18];
    const float* Aaff1 = (const float*)d_in[19];
    float* outp = (float*)d_out;

    __nv_bfloat16 *bfA, *bfB, *bfB2, *pE1, *pE2, *pTB, *pU, *pV, *pM1, *pM2, *pADJ, *pWu;
    float *ax, *ux, *e1, *e2, *tb, *m1, *m2, *sbp, *col;
    cudaGetSymbolAddress((void**)&bfA,  g_bfA);
    cudaGetSymbolAddress((void**)&bfB,  g_bfB);
    cudaGetSymbolAddress((void**)&bfB2, g_bfB2);
    cudaGetSymbolAddress((void**)&pE1,  g_pE1);
    cudaGetSymbolAddress((void**)&pE2,  g_pE2);
    cudaGetSymbolAddress((void**)&pTB,  g_pTB);
    cudaGetSymbolAddress((void**)&pU,   g_pU);
    cudaGetSymbolAddress((void**)&pV,   g_pV);
    cudaGetSymbolAddress((void**)&pM1,  g_pM1);
    cudaGetSymbolAddress((void**)&pM2,  g_pM2);
    cudaGetSymbolAddress((void**)&pADJ, g_pADJ);
    cudaGetSymbolAddress((void**)&pWu,  g_pWu);
    cudaGetSymbolAddress((void**)&ax,  g_ax);
    cudaGetSymbolAddress((void**)&ux,  g_ux);
    cudaGetSymbolAddress((void**)&e1,  g_e1);
    cudaGetSymbolAddress((void**)&e2,  g_e2);
    cudaGetSymbolAddress((void**)&tb,  g_tb);
    cudaGetSymbolAddress((void**)&m1,  g_m1);
    cudaGetSymbolAddress((void**)&m2,  g_m2);
    cudaGetSymbolAddress((void**)&sbp, g_sb);
    cudaGetSymbolAddress((void**)&col, g_col);

    cudaFuncSetAttribute(tgemm, cudaFuncAttributeMaxDynamicSharedMemorySize, SMEMT);

    const dim3 T32(32, 8);
    const long long SE = 524288;            /* 256*2048 per-batch */
    const long long SS = 65536;

    colnorm_kernel<<<32, 256>>>(A1p, col);
    colnorm_kernel<<<32, 256>>>(A2p, col + ROWS);

    /* layer-0 weights split once */
    split_tr<<<dim3(64, 32, 1), T32>>>(W0a, bfB, 1024, 2048, PW0);
    split_tr<<<dim3(64, 32, 1), T32>>>(W0u, pWu, 1024, 2048, PW0);

    /* gconv layer 0 : graph g = 1,2 */
    for (int g = 0; g < 2; g++) {
        const float* feat = g ? feat2 : feat1;
        const float* Ap   = g ? A2p : A1p;
        float* ev         = g ? e2 : e1;
        __nv_bfloat16* pE = g ? pE2 : pE1;
        const float* cv   = col + g * ROWS;
        split_rm<<<32768, 256>>>(feat, bfA, 8192LL * 1024, PFEAT);
        tgemm<<<dim3(64, 16, 1), 256, SMEMT>>>(8192, 2048, 1024, bfA, 1024, PFEAT, 0,
            bfB, 1024, PW0, 0, ax, 2048, 0, b0a, 1, cv, 0, 0, 0, 0, 0, 0, 0);
        tgemm<<<dim3(64, 16, 1), 256, SMEMT>>>(8192, 2048, 1024, bfA, 1024, PFEAT, 0,
            pWu, 1024, PW0, 0, ux, 2048, 0, b0u, 1, 0, 0, 0, 0, 0, 0, 0, 0);
        split_rm<<<8192, 256>>>(Ap, pADJ, 2097152LL, PADJ);
        split_tr<<<dim3(64, 8, 32), T32>>>(ax, bfB2, 256, 2048, PBIG);
        tgemm<<<dim3(2, 16, 32), 256, SMEMT>>>(256, 2048, 256, pADJ, 256, PADJ, SS,
            bfB2, 256, PBIG, SE, ev, 2048, SE, 0, 0, 0, ux, 2048, SE,
            pE, PBIG, 2048, SE);
    }

    /* affinity 0 + sinkhorn */
    split_tr<<<dim3(64, 64, 1), T32>>>(Aaff0, bfB, 2048, 2048, PAAF);
    tgemm<<<dim3(64, 16, 1), 256, SMEMT>>>(8192, 2048, 2048, pE1, 2048, PBIG, 0,
        bfB, 2048, PAAF, 0, tb, 2048, 0, 0, 0, 0, 0, 0, 0, pTB, PBIG, 2048, 0);
    tgemm<<<dim3(2, 2, 32), 256, SMEMT>>>(256, 256, 2048, pTB, 2048, PBIG, SE,
        pE2, 2048, PBIG, SE, sbp, 256, SS, 0, 0, 0, 0, 0, 0, 0, 0, 0, 0);
    sinkhorn_kernel<<<32, 1024>>>(sbp, sbp, n1p, skp);

    /* cross update: m1 = e1@WcT + (s@e2)@WcB + bc ; m2 = e2@WcT + (sT@e1)@WcB + bc */
    split_rm<<<8192, 256>>>(sbp, bfA, 2097152LL, PSB);
    split_tr<<<dim3(64, 8, 32), T32>>>(e2, bfB2, 256, 2048, PBIG);
    tgemm<<<dim3(2, 16, 32), 256, SMEMT>>>(256, 2048, 256, bfA, 256, PSB, SS,
        bfB2, 256, PBIG, SE, (float*)0, 0, 0, 0, 0, 0, 0, 0, 0,
        pU, PBIG, 2048, SE);                                   /* u planes   */
    split_tr<<<dim3(64, 128, 1), T32>>>(Wc, bfB, 4096, 2048, PWC);
    tgemm<<<dim3(64, 16, 1), 256, SMEMT>>>(8192, 2048, 2048, pE1, 2048, PBIG, 0,
        bfB, 4096, PWC, 0, m1, 2048, 0, bc, 0, 0, 0, 0, 0, 0, 0, 0, 0);
    tgemm<<<dim3(64, 16, 1), 256, SMEMT>>>(8192, 2048, 2048, pU, 2048, PBIG, 0,
        bfB + 2048, 4096, PWC, 0, m1, 2048, 0, 0, 0, 0, m1, 2048, 0,
        pM1, PBIG, 2048, 0);
    split_tr<<<dim3(8, 8, 32), T32>>>(sbp, bfA, 256, 256, PSB);   /* sT planes */
    split_tr<<<dim3(64, 8, 32), T32>>>(e1, bfB2, 256, 2048, PBIG);
    tgemm<<<dim3(2, 16, 32), 256, SMEMT>>>(256, 2048, 256, bfA, 256, PSB, SS,
        bfB2, 256, PBIG, SE, (float*)0, 0, 0, 0, 0, 0, 0, 0, 0,
        pV, PBIG, 2048, SE);                                   /* v planes   */
    tgemm<<<dim3(64, 16, 1), 256, SMEMT>>>(8192, 2048, 2048, pE2, 2048, PBIG, 0,
        bfB, 4096, PWC, 0, m2, 2048, 0, bc, 0, 0, 0, 0, 0, 0, 0, 0, 0);
    tgemm<<<dim3(64, 16, 1), 256, SMEMT>>>(8192, 2048, 2048, pV, 2048, PBIG, 0,
        bfB + 2048, 4096, PWC, 0, m2, 2048, 0, 0, 0, 0, m2, 2048, 0,
        pM2, PBIG, 2048, 0);

    /* layer-1 weights split once */
    split_tr<<<dim3(64, 64, 1), T32>>>(W1a, bfB, 2048, 2048, PAAF);
    split_tr<<<dim3(64, 64, 1), T32>>>(W1u, pWu, 2048, 2048, PAAF);

    /* gconv layer 1 */
    for (int g = 0; g < 2; g++) {
        const float* Ap = g ? A2p : A1p;
        float* ev       = g ? e2 : e1;
        __nv_bfloat16* pM = g ? pM2 : pM1;
        __nv_bfloat16* pE = g ? pE2 : pE1;
        const float* cv = col + g * ROWS;
        tgemm<<<dim3(64, 16, 1), 256, SMEMT>>>(8192, 2048, 2048, pM, 2048, PBIG, 0,
            bfB, 2048, PAAF, 0, ax, 2048, 0, b1a, 1, cv, 0, 0, 0, 0, 0, 0, 0);
        tgemm<<<dim3(64, 16, 1), 256, SMEMT>>>(8192, 2048, 2048, pM, 2048, PBIG, 0,
            pWu, 2048, PAAF, 0, ux, 2048, 0, b1u, 1, 0, 0, 0, 0, 0, 0, 0, 0);
        split_rm<<<8192, 256>>>(Ap, pADJ, 2097152LL, PADJ);
        split_tr<<<dim3(64, 8, 32), T32>>>(ax, bfB2, 256, 2048, PBIG);
        tgemm<<<dim3(2, 16, 32), 256, SMEMT>>>(256, 2048, 256, pADJ, 256, PADJ, SS,
            bfB2, 256, PBIG, SE, ev, 2048, SE, 0, 0, 0, ux, 2048, SE,
            pE, PBIG, 2048, SE);
    }

    /* affinity 1 + final sinkhorn */
    split_tr<<<dim3(64, 64, 1), T32>>>(Aaff1, bfB, 2048, 2048, PAAF);
    tgemm<<<dim3(64, 16, 1), 256, SMEMT>>>(8192, 2048, 2048, pE1, 2048, PBIG, 0,
        bfB, 2048, PAAF, 0, tb, 2048, 0, 0, 0, 0, 0, 0, 0, pTB, PBIG, 2048, 0);
    tgemm<<<dim3(2, 2, 32), 256, SMEMT>>>(256, 256, 2048, pTB, 2048, PBIG, SE,
        pE2, 2048, PBIG, SE, sbp, 256, SS, 0, 0, 0, 0, 0, 0, 0, 0, 0, 0);
    sinkhorn_kernel<<<32, 1024>>>(sbp, outp, n1p, skp);
}

// round 17
// speedup vs baseline: 1.0583x; 1.0001x over previous
#include <cuda_runtime.h>
#include <cuda_bf16.h>

#define NEGV (-1e9f)
#define B_   32
#define N_   256
#define CH   2048
#define ROWS (B_ * N_)                 /* 8192 */
#define KT   16

/* plane strides (elements) */
#define PFEAT 8388608LL                /* 8192x1024 */
#define PW0   2097152LL                /* 1024x2048 tr-> 2048x1024 */
#define PADJ  2097152LL                /* 32x256x256 */
#define PBIG  16777216LL               /* 8192x2048 class */
#define PAAF  4194304LL                /* 2048x2048 */
#define PWC   8388608LL                /* 2048x4096 (Wc tr) */
#define PSB   2097152LL                /* 32x256x256 */

/* smem geometry: padded rows 24 bf16 = 48 B; 4 plane-tiles per stage */
#define APAD_B  48
#define ATILE_B (128 * APAD_B)         /* 6144 B */
#define STG_B   (4 * ATILE_B)          /* 24576 B */
#define NSTG    3
#define SMEMT   (NSTG * STG_B)         /* 73728 B */

/* ------------- scratch (device globals) --------------------------------- */
__device__ __nv_bfloat16 g_bfA [2LL * 8192 * 2048];
__device__ __nv_bfloat16 g_bfB [2LL * 8192 * 2048];
__device__ __nv_bfloat16 g_bfB2[2LL * 8192 * 2048];
__device__ __nv_bfloat16 g_pE1[2LL * ROWS * CH];
__device__ __nv_bfloat16 g_pE2[2LL * ROWS * CH];
__device__ __nv_bfloat16 g_pE1T[2LL * ROWS * CH];
__device__ __nv_bfloat16 g_pE2T[2LL * ROWS * CH];
__device__ __nv_bfloat16 g_pTB[2LL * ROWS * CH];
__device__ __nv_bfloat16 g_pU [2LL * ROWS * CH];
__device__ __nv_bfloat16 g_pV [2LL * ROWS * CH];
__device__ __nv_bfloat16 g_pM1[2LL * ROWS * CH];
__device__ __nv_bfloat16 g_pM2[2LL * ROWS * CH];
__device__ __nv_bfloat16 g_pADJ[2LL * 2097152];
__device__ __nv_bfloat16 g_pWu [2LL * 4194304];
__device__ float g_ux[ROWS * CH];
__device__ float g_m1[ROWS * CH];
__device__ float g_m2[ROWS * CH];
__device__ float g_sb[B_ * N_ * N_];
__device__ float g_col[2 * ROWS];

/* ------------- low-level helpers ---------------------------------------- */
__device__ __forceinline__ void cpasync16(unsigned saddr, const void* g) {
    asm volatile("cp.async.ca.shared.global [%0], [%1], 16;" :: "r"(saddr), "l"(g));
}
#define LDSM4(r, addr) \
    asm volatile("ldmatrix.sync.aligned.m8n8.x4.shared.b16 {%0,%1,%2,%3}, [%4];" \
        : "=r"((r)[0]), "=r"((r)[1]), "=r"((r)[2]), "=r"((r)[3]) : "r"(addr))
#define MMA(d, a, b0v, b1v) \
    asm volatile("mma.sync.aligned.m16n8k16.row.col.f32.bf16.bf16.f32 " \
        "{%0,%1,%2,%3},{%4,%5,%6,%7},{%8,%9},{%0,%1,%2,%3};" \
        : "+f"((d)[0]), "+f"((d)[1]), "+f"((d)[2]), "+f"((d)[3]) \
        : "r"((a)[0]), "r"((a)[1]), "r"((a)[2]), "r"((a)[3]), "r"(b0v), "r"(b1v))

__device__ __forceinline__ void split2(float v, __nv_bfloat16& b0, __nv_bfloat16& b1) {
    b0 = __float2bfloat16(v);
    b1 = __float2bfloat16(v - __bfloat162float(b0));
}

/* ------------- tensor GEMM: C = A @ Bop^T, bf16x2 split, 3 products.
 * a0*b0 -> cm (clean fp32 chain); a0b1 + a1b0 -> cc.  R10-proven MMA order.
 * PO:  row-major split planes of the result (as split_rm would produce).
 * POT: TRANSPOSED split planes in [256-row-block][col][row%256] layout
 *      (as split_tr would produce) - rows grouped mod 256, block stride
 *      potSb.  Both bit-identical to the standalone split kernels.
 * C may be null (plane-only output).                                      */
__global__ __launch_bounds__(256) void tgemm(
    int M, int N, int K,
    const __nv_bfloat16* __restrict__ A, int lda, long long aPS, long long sAb,
    const __nv_bfloat16* __restrict__ B, int ldb, long long bPS, long long sBb,
    float* __restrict__ C, int ldc, long long sCb,
    const float* __restrict__ bias, int relu,
    const float* __restrict__ rowscale,
    const float* __restrict__ addend, int ldadd, long long sAddb,
    __nv_bfloat16* __restrict__ PO, long long poPS, int pold, long long poSb,
    __nv_bfloat16* __restrict__ POT, long long potPS, long long potSb)
{
    extern __shared__ unsigned char smem[];
    const int bz = blockIdx.z;
    A += (long long)bz * sAb;
    B += (long long)bz * sBb;
    if (C)      C += (long long)bz * sCb;
    if (addend) addend += (long long)bz * sAddb;
    if (PO)     PO += (long long)bz * poSb;
    if (POT)    POT += (long long)bz * potSb;
    const int m0 = blockIdx.x * 128, n0 = blockIdx.y * 128;
    const int tid = threadIdx.x, lane = tid & 31, wid = tid >> 5;
    const unsigned sb = (unsigned)__cvta_generic_to_shared(smem);

    const int cr = tid >> 1, ck = tid & 1;
    const __nv_bfloat16* aG = A + (long long)(m0 + cr) * lda + ck * 8;
    const __nv_bfloat16* bG = B + (long long)(n0 + cr) * ldb + ck * 8;
    const unsigned aS = sb + cr * APAD_B + ck * 16;
    const unsigned bS = sb + 2 * ATILE_B + cr * APAD_B + ck * 16;

    const int nst = K >> 4;
#define TISSUE(t, st) do {                                                \
        long long ko = (long long)(t) * KT;                               \
        _Pragma("unroll")                                                 \
        for (int p = 0; p < 2; p++) {                                     \
            cpasync16(aS + (st) * STG_B + p * ATILE_B, aG + p * aPS + ko);\
            cpasync16(bS + (st) * STG_B + p * ATILE_B, bG + p * bPS + ko);\
        }                                                                 \
        asm volatile("cp.async.commit_group;");                           \
    } while (0)

    TISSUE(0, 0);
    if (nst > 1) TISSUE(1, 1);

    float cm[2][8][4], cc[2][8][4];
#pragma unroll
    for (int i = 0; i < 2; i++)
#pragma unroll
        for (int j = 0; j < 8; j++)
#pragma unroll
            for (int k = 0; k < 4; k++) { cm[i][j][k] = 0.f; cc[i][j][k] = 0.f; }

    const int mw = (wid & 3) * 32, nw = (wid >> 2) * 64;
    const int q = lane >> 3, rl = lane & 7;
    const unsigned aoff = (mw + rl + (q & 1) * 8) * APAD_B + (q >> 1) * 16;
    const unsigned boff = 2 * ATILE_B + (nw + rl + (q & 1) * 8) * APAD_B + (q >> 1) * 16;

    int st = 0;
    for (int t = 0; t < nst; ++t) {
        if (t + 1 < nst) asm volatile("cp.async.wait_group 1;");
        else             asm volatile("cp.async.wait_group 0;");
        __syncthreads();
        if (t + 2 < nst) {
            int s2 = st + 2; if (s2 >= NSTG) s2 -= NSTG;
            TISSUE(t + 2, s2);
        }
        const unsigned sa = sb + st * STG_B + aoff;
        const unsigned sB2 = sb + st * STG_B + boff;

        unsigned a[2][2][4];
#pragma unroll
        for (int p = 0; p < 2; p++)
#pragma unroll
            for (int mi = 0; mi < 2; mi++)
                LDSM4(a[p][mi], sa + p * ATILE_B + mi * 16 * APAD_B);

#pragma unroll
        for (int ng = 0; ng < 4; ng++) {
            unsigned bf[2][4];
#pragma unroll
            for (int p = 0; p < 2; p++)
                LDSM4(bf[p], sB2 + p * ATILE_B + ng * 16 * APAD_B);
#pragma unroll
            for (int mi = 0; mi < 2; mi++)
#pragma unroll
                for (int j = 0; j < 2; j++) {
                    float* dm = cm[mi][ng * 2 + j];
                    float* dc = cc[mi][ng * 2 + j];
                    MMA(dm, a[0][mi], bf[0][j], bf[0][j + 2]);
                    MMA(dc, a[0][mi], bf[1][j], bf[1][j + 2]);
                    MMA(dc, a[1][mi], bf[0][j], bf[0][j + 2]);
                }
        }
        __syncthreads();
        if (++st == NSTG) st = 0;
    }
#undef TISSUE

    /* epilogue: c-frag (mi): rows g/g+8, cols tg*2, tg*2+1 */
    const int g = lane >> 2, tg = lane & 3;
#pragma unroll
    for (int mi = 0; mi < 2; mi++) {
        const int r0 = m0 + mw + mi * 16 + g;
        const int r1 = r0 + 8;
        const float rs0 = rowscale ? rowscale[r0] : 1.f;
        const float rs1 = rowscale ? rowscale[r1] : 1.f;
#pragma unroll
        for (int nf = 0; nf < 8; nf++) {
            const int col = n0 + nw + nf * 8 + tg * 2;
            float o0 = cm[mi][nf][0] + cc[mi][nf][0];
            float o1 = cm[mi][nf][1] + cc[mi][nf][1];
            float o2 = cm[mi][nf][2] + cc[mi][nf][2];
            float o3 = cm[mi][nf][3] + cc[mi][nf][3];
            if (bias) {
                float bv0 = bias[col], bv1 = bias[col + 1];
                o0 += bv0; o1 += bv1; o2 += bv0; o3 += bv1;
            }
            if (relu) {
                o0 = fmaxf(o0, 0.f); o1 = fmaxf(o1, 0.f);
                o2 = fmaxf(o2, 0.f); o3 = fmaxf(o3, 0.f);
            }
            o0 *= rs0; o1 *= rs0; o2 *= rs1; o3 *= rs1;
            if (addend) {
                o0 += addend[(long long)r0 * ldadd + col];
                o1 += addend[(long long)r0 * ldadd + col + 1];
                o2 += addend[(long long)r1 * ldadd + col];
                o3 += addend[(long long)r1 * ldadd + col + 1];
            }
            if (C) {
                *(float2*)(C + (long long)r0 * ldc + col) = make_float2(o0, o1);
                *(float2*)(C + (long long)r1 * ldc + col) = make_float2(o2, o3);
            }
            if (PO) {
                __nv_bfloat16 q00, q01, q10, q11, h00, h01, h10, h11;
                split2(o0, q00, h00); split2(o1, q01, h01);
                split2(o2, q10, h10); split2(o3, q11, h11);
                __nv_bfloat162 t;
                t.x = q00; t.y = q01;
                *(__nv_bfloat162*)(PO + (long long)r0 * pold + col) = t;
                t.x = h00; t.y = h01;
                *(__nv_bfloat162*)(PO + poPS + (long long)r0 * pold + col) = t;
                t.x = q10; t.y = q11;
                *(__nv_bfloat162*)(PO + (long long)r1 * pold + col) = t;
                t.x = h10; t.y = h11;
                *(__nv_bfloat162*)(PO + poPS + (long long)r1 * pold + col) = t;
            }
            if (POT) {
                __nv_bfloat16 qb, hb;
                const long long blk = (long long)(r0 >> 8) * potSb;
                const int rr0 = r0 & 255, rr1 = r1 & 255;
                __nv_bfloat16* c0 = POT + blk + (long long)col * 256;
                __nv_bfloat16* c1 = c0 + 256;
                split2(o0, qb, hb); c0[rr0] = qb; c0[potPS + rr0] = hb;
                split2(o1, qb, hb); c1[rr0] = qb; c1[potPS + rr0] = hb;
                split2(o2, qb, hb); c0[rr1] = qb; c0[potPS + rr1] = hb;
                split2(o3, qb, hb); c1[rr1] = qb; c1[potPS + rr1] = hb;
            }
        }
    }
}

/* ------------- split kernels (inputs / weight operands only) ------------ */
__global__ void split_rm(const float* __restrict__ in, __nv_bfloat16* __restrict__ out,
                         long long n, long long PS)
{
    long long i = (long long)blockIdx.x * blockDim.x + threadIdx.x;
    if (i >= n) return;
    __nv_bfloat16 b0, b1;
    split2(in[i], b0, b1);
    out[i] = b0; out[PS + i] = b1;
}
/* transpose + split: in [z][R][C] fp32 -> planes [z][C][R] bf16 */
__global__ void split_tr(const float* __restrict__ in, __nv_bfloat16* __restrict__ out,
                         int R, int C, long long PS)
{
    __shared__ float t[32][33];
    const long long zo = (long long)blockIdx.z * R * C;
    const float* ip = in + zo;
    __nv_bfloat16* op = out + zo;
    int x = blockIdx.x * 32 + threadIdx.x;
    int y0 = blockIdx.y * 32 + threadIdx.y;
#pragma unroll
    for (int j = 0; j < 32; j += 8)
        t[threadIdx.y + j][threadIdx.x] = ip[(long long)(y0 + j) * C + x];
    __syncthreads();
    int xo = blockIdx.y * 32 + threadIdx.x;
    int yo = blockIdx.x * 32 + threadIdx.y;
#pragma unroll
    for (int j = 0; j < 32; j += 8) {
        __nv_bfloat16 b0, b1;
        split2(t[threadIdx.x][threadIdx.y + j], b0, b1);
        long long oi = (long long)(yo + j) * R + xo;
        op[oi] = b0; op[PS + oi] = b1;
    }
}

/* ------------- colnorm --------------------------------------------------- */
__global__ void colnorm_kernel(const float* __restrict__ A, float* __restrict__ inv)
{
    int g = blockIdx.x * blockDim.x + threadIdx.x;
    int b = g >> 8, m = g & 255;
    const float* base = A + (long long)b * 65536 + m;
    float s = 0.f;
#pragma unroll 8
    for (int n = 0; n < 256; n++) s += fabsf(base[n * 256]);
    inv[g] = 1.f / fmaxf(s, 1e-12f);
}

/* ------------- masked Sinkhorn ------------------------------------------- */
__global__ __launch_bounds__(1024) void sinkhorn_kernel(
    float* __restrict__ buf, float* __restrict__ out,
    const int* __restrict__ n1, const int* __restrict__ iters_ptr)
{
    __shared__ float red[4 * 256];
    __shared__ float lsebuf[256];
    const int b = blockIdx.x;
    float* Mb = buf + (long long)b * 65536;
    const int nv = n1[b];
    const int iters = *iters_ptr;
    const int tid = threadIdx.x;
    const int warp = tid >> 5, lane = tid & 31;

    for (int idx = tid; idx < 65536; idx += 1024) {
        int r = idx >> 8;
        float v = Mb[idx];
        Mb[idx] = (r < nv) ? v / 0.05f : NEGV;
    }
    __syncthreads();
    for (int it = 0; it < iters; ++it) {
        if ((it & 1) == 0) {
            for (int r = warp; r < 256; r += 32) {
                float* rp = Mb + (r << 8);
                float v[8];
#pragma unroll
                for (int j = 0; j < 8; j++) v[j] = rp[lane + (j << 5)];
                float mx = v[0];
#pragma unroll
                for (int j = 1; j < 8; j++) mx = fmaxf(mx, v[j]);
#pragma unroll
                for (int o = 16; o > 0; o >>= 1)
                    mx = fmaxf(mx, __shfl_xor_sync(0xffffffffu, mx, o));
                float sm = 0.f;
#pragma unroll
                for (int j = 0; j < 8; j++) sm += expf(v[j] - mx);
#pragma unroll
                for (int o = 16; o > 0; o >>= 1)
                    sm += __shfl_xor_sync(0xffffffffu, sm, o);
                float lse = mx + logf(sm);
                bool ok = r < nv;
#pragma unroll
                for (int j = 0; j < 8; j++)
                    rp[lane + (j << 5)] = ok ? (v[j] - lse) : NEGV;
            }
            __syncthreads();
        } else {
            const int c = tid & 255, g = tid >> 8;
            float pm = NEGV;
            for (int r = g; r < 256; r += 4) pm = fmaxf(pm, Mb[(r << 8) + c]);
            red[(g << 8) + c] = pm;
            __syncthreads();
            if (tid < 256)
                lsebuf[tid] = fmaxf(fmaxf(red[tid], red[256 + tid]),
                                    fmaxf(red[512 + tid], red[768 + tid]));
            __syncthreads();
            float cmv = lsebuf[c];
            float ps = 0.f;
            for (int r = g; r < 256; r += 4) ps += expf(Mb[(r << 8) + c] - cmv);
            red[(g << 8) + c] = ps;
            __syncthreads();
            if (tid < 256)
                lsebuf[tid] = lsebuf[tid] + logf(red[tid] + red[256 + tid] +
                                                 red[512 + tid] + red[768 + tid]);
            __syncthreads();
            for (int idx = tid; idx < 65536; idx += 1024) {
                int r = idx >> 8, cc2 = idx & 255;
                Mb[idx] = (r < nv) ? (Mb[idx] - lsebuf[cc2]) : NEGV;
            }
            __syncthreads();
        }
    }
    float* ob = out + (long long)b * 65536;
    for (int idx = tid; idx < 65536; idx += 1024)
        ob[idx] = expf(Mb[idx]);
}

/* ------------- orchestration -------------------------------------------- */
extern "C" void kernel_launch(void* const* d_in, const int* in_sizes, int n_in,
                              void* d_out, int out_size)
{
    (void)in_sizes; (void)n_in; (void)out_size;
    const float* feat1 = (const float*)d_in[0];
    const float* feat2 = (const float*)d_in[1];
    const float* A1p   = (const float*)d_in[2];
    const float* A2p   = (const float*)d_in[3];
    const int*   n1p   = (const int*)d_in[4];
    const int*   skp   = (const int*)d_in[7];
    const float* W0a = (const float*)d_in[8],  *b0a = (const float*)d_in[9];
    const float* W0u = (const float*)d_in[10], *b0u = (const float*)d_in[11];
    const float* W1a = (const float*)d_in[12], *b1a = (const float*)d_in[13];
    const float* W1u = (const float*)d_in[14], *b1u = (const float*)d_in[15];
    const float* Wc  = (const float*)d_in[16], *bc  = (const float*)d_in[17];
    const float* Aaff0 = (const float*)d_in[18];
    const float* Aaff1 = (const float*)d_in[19];
    float* outp = (float*)d_out;

    __nv_bfloat16 *bfA, *bfB, *bfB2, *pE1, *pE2, *pE1T, *pE2T, *pTB, *pU, *pV,
                  *pM1, *pM2, *pADJ, *pWu;
    float *ux, *m1, *m2, *sbp, *col;
    cudaGetSymbolAddress((void**)&bfA,  g_bfA);
    cudaGetSymbolAddress((void**)&bfB,  g_bfB);
    cudaGetSymbolAddress((void**)&bfB2, g_bfB2);
    cudaGetSymbolAddress((void**)&pE1,  g_pE1);
    cudaGetSymbolAddress((void**)&pE2,  g_pE2);
    cudaGetSymbolAddress((void**)&pE1T, g_pE1T);
    cudaGetSymbolAddress((void**)&pE2T, g_pE2T);
    cudaGetSymbolAddress((void**)&pTB,  g_pTB);
    cudaGetSymbolAddress((void**)&pU,   g_pU);
    cudaGetSymbolAddress((void**)&pV,   g_pV);
    cudaGetSymbolAddress((void**)&pM1,  g_pM1);
    cudaGetSymbolAddress((void**)&pM2,  g_pM2);
    cudaGetSymbolAddress((void**)&pADJ, g_pADJ);
    cudaGetSymbolAddress((void**)&pWu,  g_pWu);
    cudaGetSymbolAddress((void**)&ux,  g_ux);
    cudaGetSymbolAddress((void**)&m1,  g_m1);
    cudaGetSymbolAddress((void**)&m2,  g_m2);
    cudaGetSymbolAddress((void**)&sbp, g_sb);
    cudaGetSymbolAddress((void**)&col, g_col);

    cudaFuncSetAttribute(tgemm, cudaFuncAttributeMaxDynamicSharedMemorySize, SMEMT);

    const dim3 T32(32, 8);
    const long long SE = 524288;            /* 256*2048 per-batch */
    const long long SS = 65536;

    colnorm_kernel<<<32, 256>>>(A1p, col);
    colnorm_kernel<<<32, 256>>>(A2p, col + ROWS);

    /* layer-0 weights split once */
    split_tr<<<dim3(64, 32, 1), T32>>>(W0a, bfB, 1024, 2048, PW0);
    split_tr<<<dim3(64, 32, 1), T32>>>(W0u, pWu, 1024, 2048, PW0);

    /* gconv layer 0 : graph g = 1,2 */
    for (int g = 0; g < 2; g++) {
        const float* feat = g ? feat2 : feat1;
        const float* Ap   = g ? A2p : A1p;
        __nv_bfloat16* pE  = g ? pE2 : pE1;
        __nv_bfloat16* pET = g ? pE2T : pE1T;
        const float* cv   = col + g * ROWS;
        split_rm<<<32768, 256>>>(feat, bfA, 8192LL * 1024, PFEAT);
        /* ax: no fp32 out, transposed planes straight into bfB2 */
        tgemm<<<dim3(64, 16, 1), 256, SMEMT>>>(8192, 2048, 1024, bfA, 1024, PFEAT, 0,
            bfB, 1024, PW0, 0, (float*)0, 0, 0, b0a, 1, cv, 0, 0, 0,
            0, 0, 0, 0, bfB2, PBIG, SE);
        tgemm<<<dim3(64, 16, 1), 256, SMEMT>>>(8192, 2048, 1024, bfA, 1024, PFEAT, 0,
            pWu, 1024, PW0, 0, ux, 2048, 0, b0u, 1, 0, 0, 0, 0,
            0, 0, 0, 0, 0, 0, 0);
        split_rm<<<8192, 256>>>(Ap, pADJ, 2097152LL, PADJ);
        /* ev: planes only (row-major pE + transposed pET for cross update) */
        tgemm<<<dim3(2, 16, 32), 256, SMEMT>>>(256, 2048, 256, pADJ, 256, PADJ, SS,
            bfB2, 256, PBIG, SE, (float*)0, 0, 0, 0, 0, 0, ux, 2048, SE,
            pE, PBIG, 2048, SE, pET, PBIG, SE);
    }

    /* affinity 0 + sinkhorn */
    split_tr<<<dim3(64, 64, 1), T32>>>(Aaff0, bfB, 2048, 2048, PAAF);
    tgemm<<<dim3(64, 16, 1), 256, SMEMT>>>(8192, 2048, 2048, pE1, 2048, PBIG, 0,
        bfB, 2048, PAAF, 0, (float*)0, 0, 0, 0, 0, 0, 0, 0, 0,
        pTB, PBIG, 2048, 0, 0, 0, 0);
    tgemm<<<dim3(2, 2, 32), 256, SMEMT>>>(256, 256, 2048, pTB, 2048, PBIG, SE,
        pE2, 2048, PBIG, SE, sbp, 256, SS, 0, 0, 0, 0, 0, 0,
        0, 0, 0, 0, 0, 0, 0);
    sinkhorn_kernel<<<32, 1024>>>(sbp, sbp, n1p, skp);

    /* cross update: m1 = e1@WcT + (s@e2)@WcB + bc ; m2 = e2@WcT + (sT@e1)@WcB + bc */
    split_rm<<<8192, 256>>>(sbp, bfA, 2097152LL, PSB);
    tgemm<<<dim3(2, 16, 32), 256, SMEMT>>>(256, 2048, 256, bfA, 256, PSB, SS,
        pE2T, 256, PBIG, SE, (float*)0, 0, 0, 0, 0, 0, 0, 0, 0,
        pU, PBIG, 2048, SE, 0, 0, 0);                          /* u planes   */
    split_tr<<<dim3(64, 128, 1), T32>>>(Wc, bfB, 4096, 2048, PWC);
    tgemm<<<dim3(64, 16, 1), 256, SMEMT>>>(8192, 2048, 2048, pE1, 2048, PBIG, 0,
        bfB, 4096, PWC, 0, m1, 2048, 0, bc, 0, 0, 0, 0, 0,
        0, 0, 0, 0, 0, 0, 0);
    tgemm<<<dim3(64, 16, 1), 256, SMEMT>>>(8192, 2048, 2048, pU, 2048, PBIG, 0,
        bfB + 2048, 4096, PWC, 0, (float*)0, 0, 0, 0, 0, 0, m1, 2048, 0,
        pM1, PBIG, 2048, 0, 0, 0, 0);
    split_tr<<<dim3(8, 8, 32), T32>>>(sbp, bfA, 256, 256, PSB);   /* sT planes */
    tgemm<<<dim3(2, 16, 32), 256, SMEMT>>>(256, 2048, 256, bfA, 256, PSB, SS,
        pE1T, 256, PBIG, SE, (float*)0, 0, 0, 0, 0, 0, 0, 0, 0,
        pV, PBIG, 2048, SE, 0, 0, 0);                          /* v planes   */
    tgemm<<<dim3(64, 16, 1), 256, SMEMT>>>(8192, 2048, 2048, pE2, 2048, PBIG, 0,
        bfB, 4096, PWC, 0, m2, 2048, 0, bc, 0, 0, 0, 0, 0,
        0, 0, 0, 0, 0, 0, 0);
    tgemm<<<dim3(64, 16, 1), 256, SMEMT>>>(8192, 2048, 2048, pV, 2048, PBIG, 0,
        bfB + 2048, 4096, PWC, 0, (float*)0, 0, 0, 0, 0, 0, m2, 2048, 0,
        pM2, PBIG, 2048, 0, 0, 0, 0);

    /* layer-1 weights split once */
    split_tr<<<dim3(64, 64, 1), T32>>>(W1a, bfB, 2048, 2048, PAAF);
    split_tr<<<dim3(64, 64, 1), T32>>>(W1u, pWu, 2048, 2048, PAAF);

    /* gconv layer 1 */
    for (int g = 0; g < 2; g++) {
        const float* Ap = g ? A2p : A1p;
        __nv_bfloat16* pM = g ? pM2 : pM1;
        __nv_bfloat16* pE = g ? pE2 : pE1;
        const float* cv = col + g * ROWS;
        tgemm<<<dim3(64, 16, 1), 256, SMEMT>>>(8192, 2048, 2048, pM, 2048, PBIG, 0,
            bfB, 2048, PAAF, 0, (float*)0, 0, 0, b1a, 1, cv, 0, 0, 0,
            0, 0, 0, 0, bfB2, PBIG, SE);
        tgemm<<<dim3(64, 16, 1), 256, SMEMT>>>(8192, 2048, 2048, pM, 2048, PBIG, 0,
            pWu, 2048, PAAF, 0, ux, 2048, 0, b1u, 1, 0, 0, 0, 0,
            0, 0, 0, 0, 0, 0, 0);
        split_rm<<<8192, 256>>>(Ap, pADJ, 2097152LL, PADJ);
        tgemm<<<dim3(2, 16, 32), 256, SMEMT>>>(256, 2048, 256, pADJ, 256, PADJ, SS,
            bfB2, 256, PBIG, SE, (float*)0, 0, 0, 0, 0, 0, ux, 2048, SE,
            pE, PBIG, 2048, SE, 0, 0, 0);
    }

    /* affinity 1 + final sinkhorn */
    split_tr<<<dim3(64, 64, 1), T32>>>(Aaff1, bfB, 2048, 2048, PAAF);
    tgemm<<<dim3(64, 16, 1), 256, SMEMT>>>(8192, 2048, 2048, pE1, 2048, PBIG, 0,
        bfB, 2048, PAAF, 0, (float*)0, 0, 0, 0, 0, 0, 0, 0, 0,
        pTB, PBIG, 2048, 0, 0, 0, 0);
    tgemm<<<dim3(2, 2, 32), 256, SMEMT>>>(256, 256, 2048, pTB, 2048, PBIG, SE,
        pE2, 2048, PBIG, SE, sbp, 256, SS, 0, 0, 0, 0, 0, 0,
        0, 0, 0, 0, 0, 0, 0);
    sinkhorn_kernel<<<32, 1024>>>(sbp, outp, n1p, skp);
}